// round 1
// baseline (speedup 1.0000x reference)
#include <cuda_runtime.h>
#include <cuda_bf16.h>

namespace {

constexpr int B  = 4096;
constexpr int C  = 256;   // circuits
constexpr int NQ = 4;     // qubits per circuit
constexpr int NS = 16;    // 2^NQ amplitudes

// CNOT(control=CQ, target=TQ): pure permutation of basis amplitudes.
// Fully unrolled with template-constant indices -> register renames, zero SASS cost.
template<int CQ, int TQ>
__device__ __forceinline__ void cnot_g(float (&re)[NS], float (&im)[NS]) {
#pragma unroll
  for (int i = 0; i < NS; ++i) {
    if (((i >> CQ) & 1) && !((i >> TQ) & 1)) {
      const int j = i | (1 << TQ);
      float t;
      t = re[i]; re[i] = re[j]; re[j] = t;
      t = im[i]; im[i] = im[j]; im[j] = t;
    }
  }
}

// RX(theta) on qubit Q with cc=cos(theta/2), ss=sin(theta/2):
//   [c, -i s; -i s, c] butterfly over pairs (i, i|bit).
template<int Q>
__device__ __forceinline__ void rx_g(float (&re)[NS], float (&im)[NS],
                                     float cc, float ss) {
#pragma unroll
  for (int i = 0; i < NS; ++i) {
    if (!((i >> Q) & 1)) {
      const int j = i | (1 << Q);
      const float ar = re[i], ai = im[i], br = re[j], bi = im[j];
      re[i] = cc * ar + ss * bi;   // (c*a - i*s*b).re
      im[i] = cc * ai - ss * br;   // (c*a - i*s*b).im
      re[j] = cc * br + ss * ai;
      im[j] = cc * bi - ss * ar;
    }
  }
}

__global__ void __launch_bounds__(256, 2)
qsim(const float* __restrict__ x, const float* __restrict__ w,
     float* __restrict__ out) {
  const int b = blockIdx.x;     // batch
  const int c = threadIdx.x;    // circuit 0..255

  // x[b, 4c .. 4c+3]  (16B coalesced)
  const float4 xv = *reinterpret_cast<const float4*>(x + (size_t)b * (C * NQ) + c * NQ);
  // weights[c, l, q] : 8 floats per circuit (L2-resident, 8KB total)
  const float4 w0 = *reinterpret_cast<const float4*>(w + c * 8);
  const float4 w1 = *reinterpret_cast<const float4*>(w + c * 8 + 4);

  // Key fusion: embedding RX(x_q) followed immediately by layer-1 RX(w0_q)
  // on the same wire => single RX(x_q + w0_q). theta/2 trig:
  float ct[NQ], st[NQ];
  __sincosf(0.5f * (xv.x + w0.x), &st[0], &ct[0]);
  __sincosf(0.5f * (xv.y + w0.y), &st[1], &ct[1]);
  __sincosf(0.5f * (xv.z + w0.z), &st[2], &ct[2]);
  __sincosf(0.5f * (xv.w + w0.w), &st[3], &ct[3]);

  // layer-2 RX trig
  float cw[NQ], sw[NQ];
  __sincosf(0.5f * w1.x, &sw[0], &cw[0]);
  __sincosf(0.5f * w1.y, &sw[1], &cw[1]);
  __sincosf(0.5f * w1.z, &sw[2], &cw[2]);
  __sincosf(0.5f * w1.w, &sw[3], &cw[3]);

  // Initial product state: amp(i) = (-i)^popc(i) * prod_q (ct or st)[q].
  // Track the real magnitude product; phase pattern is compile-time per index,
  // zeros constant-fold through the unrolled butterflies below.
  const float r01[4] = { ct[0]*ct[1], st[0]*ct[1], ct[0]*st[1], st[0]*st[1] };
  const float r23[4] = { ct[2]*ct[3], st[2]*ct[3], ct[2]*st[3], st[2]*st[3] };

  float re[NS], im[NS];
#pragma unroll
  for (int i = 0; i < NS; ++i) {
    const float r = r01[i & 3] * r23[(i >> 2) & 3];
    const int k = __popc(i) & 3;   // constant per unrolled i
    re[i] = (k == 0) ? r : ((k == 2) ? -r : 0.0f);
    im[i] = (k == 1) ? -r : ((k == 3) ? r : 0.0f);
  }

  // Layer 1: RX already fused into the initial state; entangler ring.
  cnot_g<0, 1>(re, im);
  cnot_g<1, 2>(re, im);
  cnot_g<2, 3>(re, im);
  cnot_g<3, 0>(re, im);

  // Layer 2: RX on each wire, then ring.
  rx_g<0>(re, im, cw[0], sw[0]);
  rx_g<1>(re, im, cw[1], sw[1]);
  rx_g<2>(re, im, cw[2], sw[2]);
  rx_g<3>(re, im, cw[3], sw[3]);
  cnot_g<0, 1>(re, im);
  cnot_g<1, 2>(re, im);
  cnot_g<2, 3>(re, im);
  cnot_g<3, 0>(re, im);

  // Probabilities and <Z_q> = sum_i p_i * (1 - 2*bit_q(i)).
  float p[NS];
#pragma unroll
  for (int i = 0; i < NS; ++i) p[i] = re[i] * re[i] + im[i] * im[i];

  float z[NQ];
#pragma unroll
  for (int q = 0; q < NQ; ++q) {
    float a = 0.0f;
#pragma unroll
    for (int i = 0; i < NS; ++i) a = ((i >> q) & 1) ? (a - p[i]) : (a + p[i]);
    z[q] = a;
  }

  // out[b, 4c + q]  (16B coalesced)
  *reinterpret_cast<float4*>(out + (size_t)b * (C * NQ) + c * NQ) =
      make_float4(z[0], z[1], z[2], z[3]);
}

}  // namespace

extern "C" void kernel_launch(void* const* d_in, const int* in_sizes, int n_in,
                              void* d_out, int out_size) {
  (void)in_sizes; (void)n_in; (void)out_size;
  const float* x = reinterpret_cast<const float*>(d_in[0]);
  const float* w = reinterpret_cast<const float*>(d_in[1]);
  float* out = reinterpret_cast<float*>(d_out);
  qsim<<<B, C>>>(x, w, out);
}

// round 2
// speedup vs baseline: 1.8519x; 1.8519x over previous
#include <cuda_runtime.h>
#include <cuda_bf16.h>

namespace {

constexpr int B = 4096;
constexpr int C = 256;

// Closed-form Pauli expansion of the NQ=4, L=2 BasicEntanglerLayers circuit.
// U = E * RX(w1) * E * RX(x + w0)  on |0000>, E = CNOT ring (0,1)(1,2)(2,3)(3,0).
// Per-qubit expectations in RX(phi)|0>: <Z>=cos(phi), <Y>=-sin(phi), <X>=0.
__global__ void __launch_bounds__(256)
qlin(const float* __restrict__ x, const float* __restrict__ w,
     float* __restrict__ out) {
  const int b = blockIdx.x;   // batch row
  const int c = threadIdx.x;  // circuit

  const float4 xv = *reinterpret_cast<const float4*>(x + (size_t)b * (C * 4) + c * 4);
  const float4 w0 = *reinterpret_cast<const float4*>(w + c * 8);
  const float4 w1 = *reinterpret_cast<const float4*>(w + c * 8 + 4);

  // Data-dependent trig: phi_q = x_q + w0_q  (embedding RX fused with layer-1 RX).
  float S0, C0, S1, C1, S2, C2, S3, C3;
  __sincosf(xv.x + w0.x, &S0, &C0);
  __sincosf(xv.y + w0.y, &S1, &C1);
  __sincosf(xv.z + w0.z, &S2, &C2);
  __sincosf(xv.w + w0.w, &S3, &C3);

  // Layer-2 trig (depends only on circuit; recompute per thread, it's cheap).
  float s0, c0, s1, c1, s2, c2, s3, c3;
  __sincosf(w1.x, &s0, &c0);
  __sincosf(w1.y, &s1, &c1);
  __sincosf(w1.z, &s2, &c2);
  __sincosf(w1.w, &s3, &c3);

  // Weight-only products.
  const float A = c0 * c1, Bv = s0 * s1, P = c0 * s1, Q = s0 * c1;
  const float D = c1 * c2, E = s1 * s2, F = c2 * c3, G = s2 * s3;

  // Shared data products.
  const float C02 = C0 * C2, S02 = S0 * S2;
  const float SC  = S0 * C2, CS  = C0 * S2;
  const float C13 = C1 * C3, S13 = S1 * S3;

  // <Z1> and <Z3> share u, v.
  const float u = fmaf(A, C02, Bv * S02);
  const float v = fmaf(P, SC, Q * CS);
  const float Z1 = C3 * u;
  const float Z3 = fmaf(F, u, G * v);

  // <Z0>.
  const float t1 = fmaf(c3, C0 * C13, s3 * (S0 * S13));
  const float t2 = fmaf(c3, C0 * S13, s3 * (S0 * C13));
  const float Z0 = fmaf(D, t1, E * t2);

  // <Z2>.
  const float Z2 = c0 * fmaf(D, C13, E * S13);

  *reinterpret_cast<float4*>(out + (size_t)b * (C * 4) + c * 4) =
      make_float4(Z0, Z1, Z2, Z3);
}

}  // namespace

extern "C" void kernel_launch(void* const* d_in, const int* in_sizes, int n_in,
                              void* d_out, int out_size) {
  (void)in_sizes; (void)n_in; (void)out_size;
  const float* x = reinterpret_cast<const float*>(d_in[0]);
  const float* w = reinterpret_cast<const float*>(d_in[1]);
  float* out = reinterpret_cast<float*>(d_out);
  qlin<<<B, C>>>(x, w, out);
}

// round 3
// speedup vs baseline: 2.2222x; 1.2000x over previous
#include <cuda_runtime.h>
#include <cuda_bf16.h>

namespace {

constexpr int B = 4096;
constexpr int C = 256;
constexpr int R = 4;   // batch rows per thread

// Closed-form Pauli expansion of the NQ=4, L=2 BasicEntanglerLayers circuit.
// U = E * RX(w1) * E * RX(x + w0) on |0000>, E = CNOT ring (0,1)(1,2)(2,3)(3,0).
// Weight-only trig/products are computed once per thread and reused for R rows.
__global__ void __launch_bounds__(256)
qlin(const float* __restrict__ x, const float* __restrict__ w,
     float* __restrict__ out) {
  const int c  = threadIdx.x;          // circuit
  const int b0 = blockIdx.x * R;       // first batch row of this block

  // Issue all independent DRAM loads first (MLP = R).
  float4 xr[R];
#pragma unroll
  for (int r = 0; r < R; ++r)
    xr[r] = *reinterpret_cast<const float4*>(x + (size_t)(b0 + r) * (C * 4) + c * 4);

  const float4 w0 = *reinterpret_cast<const float4*>(w + c * 8);      // L2-hot
  const float4 w1 = *reinterpret_cast<const float4*>(w + c * 8 + 4);

  // Per-circuit (weight-only) trig — amortized over R rows.
  float s0, c0, s1, c1, s2, c2, s3, c3;
  __sincosf(w1.x, &s0, &c0);
  __sincosf(w1.y, &s1, &c1);
  __sincosf(w1.z, &s2, &c2);
  __sincosf(w1.w, &s3, &c3);

  const float A = c0 * c1, Bv = s0 * s1, P = c0 * s1, Q = s0 * c1;
  const float D = c1 * c2, E = s1 * s2, F = c2 * c3, G = s2 * s3;

  float4 zr[R];
#pragma unroll
  for (int r = 0; r < R; ++r) {
    // Data-dependent trig: phi_q = x_q + w0_q (embedding RX fused with layer-1 RX).
    float S0, C0, S1, C1, S2, C2, S3, C3;
    __sincosf(xr[r].x + w0.x, &S0, &C0);
    __sincosf(xr[r].y + w0.y, &S1, &C1);
    __sincosf(xr[r].z + w0.z, &S2, &C2);
    __sincosf(xr[r].w + w0.w, &S3, &C3);

    const float C02 = C0 * C2, S02 = S0 * S2;
    const float SC  = S0 * C2, CS  = C0 * S2;
    const float C13 = C1 * C3, S13 = S1 * S3;

    const float u = fmaf(A, C02, Bv * S02);
    const float v = fmaf(P, SC, Q * CS);
    const float Z1 = C3 * u;
    const float Z3 = fmaf(F, u, G * v);

    const float t1 = fmaf(c3, C0 * C13, s3 * (S0 * S13));
    const float t2 = fmaf(c3, C0 * S13, s3 * (S0 * C13));
    const float Z0 = fmaf(D, t1, E * t2);

    const float Z2 = c0 * fmaf(D, C13, E * S13);

    zr[r] = make_float4(Z0, Z1, Z2, Z3);
  }

#pragma unroll
  for (int r = 0; r < R; ++r)
    *reinterpret_cast<float4*>(out + (size_t)(b0 + r) * (C * 4) + c * 4) = zr[r];
}

}  // namespace

extern "C" void kernel_launch(void* const* d_in, const int* in_sizes, int n_in,
                              void* d_out, int out_size) {
  (void)in_sizes; (void)n_in; (void)out_size;
  const float* x = reinterpret_cast<const float*>(d_in[0]);
  const float* w = reinterpret_cast<const float*>(d_in[1]);
  float* out = reinterpret_cast<float*>(d_out);
  qlin<<<B / R, C>>>(x, w, out);
}